// round 8
// baseline (speedup 1.0000x reference)
#include <cuda_runtime.h>
#include <cuda_bf16.h>

// Problem constants (from reference)
#define GX 352
#define GY 400
#define GZ 1
#define BSZ 4
#define NSEG (BSZ * GZ * GY * GX)   // 563200
#define NPTS 2000000
#define CH 4

// Output layout: [ mean: NSEG*4 f32 ][ counts: NSEG f32 ]

// ---- Phase 0: zero the output (11.26 MB, one float4 per thread).
// Trigger PDL completion FIRST so the scatter kernel launches and runs its
// prefetch while we are still filling; scatter's GridDependencySynchronize
// still waits for this grid to fully finish before any atomic fires. ----
__global__ void __launch_bounds__(256)
zero_kernel(float4* __restrict__ out4) {
    cudaTriggerProgrammaticLaunchCompletion();        // release successor launch NOW
    const int n4 = (NSEG * CH + NSEG) / 4;            // 704000
    int i = blockIdx.x * blockDim.x + threadIdx.x;
    if (i < n4)
        out4[i] = make_float4(0.f, 0.f, 0.f, 0.f);
}

// ---- Phase 1: scatter. Prefetch point data BEFORE the PDL sync so the
//      stream-load latency overlaps the zero kernel's execution. ----
__global__ void __launch_bounds__(256)
scatter_kernel(const float4* __restrict__ feats,
               const int4* __restrict__ coors,
               float4* __restrict__ sums,
               float* __restrict__ counts) {
    int i = blockIdx.x * blockDim.x + threadIdx.x;
    int4  c;
    float4 f;
    bool valid = (i < NPTS);
    if (valid) {
        c = coors[i];                                 // independent of bins
        f = feats[i];
    }
    cudaTriggerProgrammaticLaunchCompletion();        // let finalize launch early too
    cudaGridDependencySynchronize();                  // zero grid fully done
    if (valid) {
        int seg = ((c.x * GZ + c.y) * GY + c.z) * GX + c.w;
        atomicAdd(&sums[seg], f);                     // RED.128 (L2-resident)
        atomicAdd(&counts[seg], 1.0f);                // RED.32
    }
}

// ---- Phase 2: in-place mean = sums / max(count,1) ----
__global__ void __launch_bounds__(256)
finalize_kernel(float4* __restrict__ sums,
                const float* __restrict__ counts) {
    int s = blockIdx.x * blockDim.x + threadIdx.x;
    cudaGridDependencySynchronize();                  // all REDs visible
    if (s >= NSEG) return;
    float cnt = counts[s];
    float inv = 1.0f / fmaxf(cnt, 1.0f);
    float4 v = sums[s];
    v.x *= inv; v.y *= inv; v.z *= inv; v.w *= inv;
    sums[s] = v;
}

static inline void launch_pdl(void* func, dim3 grid, dim3 block,
                              void** args, bool pdl) {
    cudaLaunchConfig_t cfg = {};
    cfg.gridDim = grid;
    cfg.blockDim = block;
    cfg.dynamicSmemBytes = 0;
    cfg.stream = 0;                                   // capture (legacy) stream
    cudaLaunchAttribute attr[1];
    if (pdl) {
        attr[0].id = cudaLaunchAttributeProgrammaticStreamSerialization;
        attr[0].val.programmaticStreamSerializationAllowed = 1;
        cfg.attrs = attr;
        cfg.numAttrs = 1;
    }
    cudaLaunchKernelExC(&cfg, func, args);
}

extern "C" void kernel_launch(void* const* d_in, const int* in_sizes, int n_in,
                              void* d_out, int out_size) {
    const float4* feats = (const float4*)d_in[0];     // (NPTS, 4) f32
    const int4*   coors = (const int4*)d_in[1];       // (NPTS, 4) i32
    float* out = (float*)d_out;

    float4* sums   = (float4*)out;                    // NSEG float4
    float*  counts = out + (size_t)NSEG * CH;         // NSEG floats

    // 0) zero output: one-shot, 704000 float4s -> 2750 blocks of 256
    {
        float4* out4 = (float4*)out;
        void* args[] = { &out4 };
        launch_pdl((void*)zero_kernel, dim3((704000 + 255) / 256), dim3(256),
                   args, false);
    }

    // 1) scatter (PDL: launches + prefetches while zero fills)
    {
        void* args[] = { (void*)&feats, (void*)&coors, &sums, &counts };
        int blocks = (NPTS + 255) / 256;
        launch_pdl((void*)scatter_kernel, dim3(blocks), dim3(256), args, true);
    }

    // 2) finalize (PDL: launch overlaps scatter execution)
    {
        void* args[] = { &sums, &counts };
        int blocks = (NSEG + 255) / 256;
        launch_pdl((void*)finalize_kernel, dim3(blocks), dim3(256), args, true);
    }
}

// round 9
// speedup vs baseline: 1.0457x; 1.0457x over previous
#include <cuda_runtime.h>
#include <cuda_bf16.h>

// Problem constants (from reference)
#define GX 352
#define GY 400
#define GZ 1
#define BSZ 4
#define NSEG (BSZ * GZ * GY * GX)   // 563200
#define NPTS 2000000
#define CH 4

// Output layout: [ mean: NSEG*4 f32 ][ counts: NSEG f32 ]

// ---- Phase 0: zero the output (704000 float4s, 2 per thread -> 1375 blocks).
// Trigger at the END: only the scatter's launch ramp overlaps us; its CTAs
// never spin-occupy SMs while we're still filling (R8 failure mode). ----
__global__ void __launch_bounds__(256)
zero_kernel(float4* __restrict__ out4) {
    const int n4 = (NSEG * CH + NSEG) / 4;            // 704000
    int i = blockIdx.x * (blockDim.x * 2) + threadIdx.x;
    if (i < n4)              out4[i]              = make_float4(0.f, 0.f, 0.f, 0.f);
    if (i + 256 < n4)        out4[i + 256]        = make_float4(0.f, 0.f, 0.f, 0.f);
    cudaTriggerProgrammaticLaunchCompletion();
}

// ---- Phase 1: scatter. Prefetch point data BEFORE the PDL sync so the
//      stream-load latency overlaps the zero kernel tail + our launch ramp. ----
__global__ void __launch_bounds__(256)
scatter_kernel(const float4* __restrict__ feats,
               const int4* __restrict__ coors,
               float4* __restrict__ sums,
               float* __restrict__ counts) {
    int i = blockIdx.x * blockDim.x + threadIdx.x;
    int4  c;
    float4 f;
    bool valid = (i < NPTS);
    if (valid) {
        c = coors[i];                                 // independent of bins
        f = feats[i];
    }
    cudaTriggerProgrammaticLaunchCompletion();        // all-CTA trigger ~= scatter end
    cudaGridDependencySynchronize();                  // zero grid fully done
    if (valid) {
        int seg = ((c.x * GZ + c.y) * GY + c.z) * GX + c.w;
        atomicAdd(&sums[seg], f);                     // RED.128 (L2-resident)
        atomicAdd(&counts[seg], 1.0f);                // RED.32
    }
}

// ---- Phase 2: in-place mean = sums / max(count,1) ----
__global__ void __launch_bounds__(256)
finalize_kernel(float4* __restrict__ sums,
                const float* __restrict__ counts) {
    int s = blockIdx.x * blockDim.x + threadIdx.x;
    cudaGridDependencySynchronize();                  // all REDs visible
    if (s >= NSEG) return;
    float cnt = counts[s];
    float inv = 1.0f / fmaxf(cnt, 1.0f);
    float4 v = sums[s];
    v.x *= inv; v.y *= inv; v.z *= inv; v.w *= inv;
    sums[s] = v;
}

static inline void launch_pdl(void* func, dim3 grid, dim3 block,
                              void** args, bool pdl) {
    cudaLaunchConfig_t cfg = {};
    cfg.gridDim = grid;
    cfg.blockDim = block;
    cfg.dynamicSmemBytes = 0;
    cfg.stream = 0;                                   // capture (legacy) stream
    cudaLaunchAttribute attr[1];
    if (pdl) {
        attr[0].id = cudaLaunchAttributeProgrammaticStreamSerialization;
        attr[0].val.programmaticStreamSerializationAllowed = 1;
        cfg.attrs = attr;
        cfg.numAttrs = 1;
    }
    cudaLaunchKernelExC(&cfg, func, args);
}

extern "C" void kernel_launch(void* const* d_in, const int* in_sizes, int n_in,
                              void* d_out, int out_size) {
    const float4* feats = (const float4*)d_in[0];     // (NPTS, 4) f32
    const int4*   coors = (const int4*)d_in[1];       // (NPTS, 4) i32
    float* out = (float*)d_out;

    float4* sums   = (float4*)out;                    // NSEG float4
    float*  counts = out + (size_t)NSEG * CH;         // NSEG floats

    // 0) zero output: 704000 float4s, 2/thread -> 1375 blocks of 256
    {
        float4* out4 = (float4*)out;
        void* args[] = { &out4 };
        launch_pdl((void*)zero_kernel, dim3((704000 + 511) / 512), dim3(256),
                   args, false);
    }

    // 1) scatter (PDL: launch ramp + prefetch overlap zero tail)
    {
        void* args[] = { (void*)&feats, (void*)&coors, &sums, &counts };
        int blocks = (NPTS + 255) / 256;
        launch_pdl((void*)scatter_kernel, dim3(blocks), dim3(256), args, true);
    }

    // 2) finalize (PDL: launch overlaps scatter execution)
    {
        void* args[] = { &sums, &counts };
        int blocks = (NSEG + 255) / 256;
        launch_pdl((void*)finalize_kernel, dim3(blocks), dim3(256), args, true);
    }
}